// round 2
// baseline (speedup 1.0000x reference)
#include <cuda_runtime.h>
#include <math.h>

#define Nn 2048
#define FD 2048
#define Hd 1024
#define G6 6144

// Persistent scratch (static device globals — no allocation at launch time).
__device__ float g_xg[(size_t)Nn * G6];        // x_gates (+ all biases), later += h-contributions
__device__ float g_px[(size_t)Nn * Hd];        // px projection
__device__ float g_c [(size_t)(Nn + 1) * Hd];  // cell state, row Nn = zero sentinel
__device__ float g_h [(size_t)(Nn + 1) * Hd];  // hidden state, row Nn = zero sentinel
__device__ float g_bias6[G6];                  // b_ioffux + b_ioffuh_l + b_ioffuh_r
__device__ float g_part[8 * 32 * G6];          // k-split partials for small chunks

// ---------------------------------------------------------------------------
// packed f32x2 helpers (FFMA2: 2 fp32 MACs per instruction on sm_100+)
// ---------------------------------------------------------------------------
__device__ __forceinline__ void fma2(unsigned long long& c, unsigned long long a,
                                     unsigned long long b) {
    asm("fma.rn.f32x2 %0, %1, %2, %0;" : "+l"(c) : "l"(a), "l"(b));
}
__device__ __forceinline__ unsigned long long dup2(float x) {
    unsigned long long d;
    asm("mov.b64 %0, {%1, %1};" : "=l"(d) : "f"(x));
    return d;
}
__device__ __forceinline__ float lo2(unsigned long long v) {
    return __uint_as_float((unsigned int)v);
}
__device__ __forceinline__ float hi2(unsigned long long v) {
    return __uint_as_float((unsigned int)(v >> 32));
}

__device__ __forceinline__ float sigmoidf_(float x) { return 1.0f / (1.0f + expf(-x)); }

// ---------------------------------------------------------------------------
// init: combine biases, zero sentinel state rows
// ---------------------------------------------------------------------------
__global__ void init_kernel(const float* __restrict__ bx, const float* __restrict__ bl,
                            const float* __restrict__ br) {
    int j = blockIdx.x * 256 + threadIdx.x;
    if (j < G6) g_bias6[j] = bx[j] + bl[j] + br[j];
    if (j < Hd) {
        g_c[(size_t)Nn * Hd + j] = 0.0f;
        g_h[(size_t)Nn * Hd + j] = 0.0f;
    }
}

// ---------------------------------------------------------------------------
// Big NT SGEMM: C[M,Nc] = A[M,K] * W[Nc,K]^T + bias   (128x128x16 tile, FFMA2)
// target==0: C=g_xg, Nc=6144, bias=g_bias6 ; target==1: C=g_px, Nc=1024, bias=bias_ext
// ---------------------------------------------------------------------------
__global__ __launch_bounds__(256) void sgemm_xproj(const float* __restrict__ A,
                                                   const float* __restrict__ W,
                                                   const float* __restrict__ bias_ext,
                                                   int target) {
    __shared__ float As[16][128];
    __shared__ float Bs[16][128];
    const int tid = threadIdx.x;
    const int tx = tid & 15, ty = tid >> 4;
    const float* Ag = A + (size_t)blockIdx.y * 128 * FD;
    const float* Wg = W + (size_t)blockIdx.x * 128 * FD;

    unsigned long long acc[8][4];
#pragma unroll
    for (int i = 0; i < 8; i++)
#pragma unroll
        for (int j = 0; j < 4; j++) acc[i][j] = 0ull;

    for (int k0 = 0; k0 < FD; k0 += 16) {
        __syncthreads();
#pragma unroll
        for (int l = 0; l < 2; l++) {
            int idx = tid + l * 256;
            int row = idx >> 2;
            int c4  = (idx & 3) << 2;
            float4 av = *(const float4*)(Ag + (size_t)row * FD + k0 + c4);
            As[c4 + 0][row] = av.x; As[c4 + 1][row] = av.y;
            As[c4 + 2][row] = av.z; As[c4 + 3][row] = av.w;
            float4 bv = *(const float4*)(Wg + (size_t)row * FD + k0 + c4);
            Bs[c4 + 0][row] = bv.x; Bs[c4 + 1][row] = bv.y;
            Bs[c4 + 2][row] = bv.z; Bs[c4 + 3][row] = bv.w;
        }
        __syncthreads();
#pragma unroll
        for (int k = 0; k < 16; k++) {
            float a[8];
            *(float4*)(a)     = *(const float4*)&As[k][ty * 4];
            *(float4*)(a + 4) = *(const float4*)&As[k][64 + ty * 4];
            ulonglong2 u0 = *(const ulonglong2*)&Bs[k][tx * 4];
            ulonglong2 u1 = *(const ulonglong2*)&Bs[k][64 + tx * 4];
            unsigned long long b2[4] = {u0.x, u0.y, u1.x, u1.y};
#pragma unroll
            for (int i = 0; i < 8; i++) {
                unsigned long long ad = dup2(a[i]);
                fma2(acc[i][0], ad, b2[0]);
                fma2(acc[i][1], ad, b2[1]);
                fma2(acc[i][2], ad, b2[2]);
                fma2(acc[i][3], ad, b2[3]);
            }
        }
    }

    float* C = target ? g_px : g_xg;
    const int Nc = target ? Hd : G6;
    const float* bias = target ? bias_ext : g_bias6;
#pragma unroll
    for (int i = 0; i < 8; i++) {
        int rr = (i < 4) ? (ty * 4 + i) : (64 + ty * 4 + (i - 4));
        int grow = blockIdx.y * 128 + rr;
#pragma unroll
        for (int j2 = 0; j2 < 4; j2++) {
            int cc = (j2 < 2) ? (tx * 4 + j2 * 2) : (64 + tx * 4 + (j2 - 2) * 2);
            int gcol = blockIdx.x * 128 + cc;
            float2 v;
            v.x = lo2(acc[i][j2]) + bias[gcol];
            v.y = hi2(acc[i][j2]) + bias[gcol + 1];
            *(float2*)&C[(size_t)grow * Nc + gcol] = v;
        }
    }
}

// ---------------------------------------------------------------------------
// Recurrent chunk GEMM (B multiple of 64): g_xg[i,:] += h[l(i)] @ WL^T + h[r(i)] @ WR^T
// A rows gathered implicitly from g_h via child index. 64x64x16 tile, FFMA2.
// grid: (6144/64, B/64)
// ---------------------------------------------------------------------------
__global__ __launch_bounds__(256) void chunk_gemm(const float* __restrict__ WL,
                                                  const float* __restrict__ WR,
                                                  int start) {
    __shared__ float As[16][64];
    __shared__ float Bs[16][64];
    const int tid = threadIdx.x;
    const int tx = tid & 15, ty = tid >> 4;

    unsigned long long acc[4][2];
#pragma unroll
    for (int i = 0; i < 4; i++) { acc[i][0] = 0ull; acc[i][1] = 0ull; }

    for (int k0 = 0; k0 < 2 * Hd; k0 += 16) {
        const float* W = (k0 < Hd) ? WL : WR;
        const int kk = k0 & (Hd - 1);
        __syncthreads();
        {
            int row = tid >> 2;
            int c4  = (tid & 3) << 2;
            int i = start + blockIdx.y * 64 + row;
            int child = (k0 < Hd) ? (2 * i + 1) : (2 * i + 2);
            if (child > Nn) child = Nn;  // sentinel (zeros)
            float4 av = *(const float4*)(g_h + (size_t)child * Hd + kk + c4);
            As[c4 + 0][row] = av.x; As[c4 + 1][row] = av.y;
            As[c4 + 2][row] = av.z; As[c4 + 3][row] = av.w;
            float4 bv = *(const float4*)(W + (size_t)(blockIdx.x * 64 + row) * Hd + kk + c4);
            Bs[c4 + 0][row] = bv.x; Bs[c4 + 1][row] = bv.y;
            Bs[c4 + 2][row] = bv.z; Bs[c4 + 3][row] = bv.w;
        }
        __syncthreads();
#pragma unroll
        for (int k = 0; k < 16; k++) {
            float4 af = *(const float4*)&As[k][ty * 4];
            ulonglong2 u0 = *(const ulonglong2*)&Bs[k][tx * 4];
            float a[4] = {af.x, af.y, af.z, af.w};
#pragma unroll
            for (int i = 0; i < 4; i++) {
                unsigned long long ad = dup2(a[i]);
                fma2(acc[i][0], ad, u0.x);
                fma2(acc[i][1], ad, u0.y);
            }
        }
    }
#pragma unroll
    for (int i = 0; i < 4; i++) {
        int grow = start + blockIdx.y * 64 + ty * 4 + i;
        float* Cp = g_xg + (size_t)grow * G6 + blockIdx.x * 64 + tx * 4;
        Cp[0] += lo2(acc[i][0]);
        Cp[1] += hi2(acc[i][0]);
        Cp[2] += lo2(acc[i][1]);
        Cp[3] += hi2(acc[i][1]);
    }
}

// ---------------------------------------------------------------------------
// Small chunk (B <= 32): K-split GEMV. grid (6144/8, 8); each warp owns one gate
// output j, computes partials over a 256-wide K slice for all B nodes.
// h slabs staged in shared memory. Partials summed in update_kernel.
// ---------------------------------------------------------------------------
template <int B>
__global__ __launch_bounds__(256) void chunk_small(const float* __restrict__ WL,
                                                   const float* __restrict__ WR,
                                                   int start) {
    __shared__ float hs[B][256];
    const int warp = threadIdx.x >> 5, lane = threadIdx.x & 31;
    const int j  = blockIdx.x * 8 + warp;
    const int ks = blockIdx.y * 256;
    const float* W = (ks < Hd) ? WL : WR;
    const int kw = ks & (Hd - 1);

    for (int idx = threadIdx.x; idx < B * 256; idx += 256) {
        int m = idx >> 8, kk = idx & 255;
        int i = start + m;
        int child = (ks < Hd) ? (2 * i + 1) : (2 * i + 2);
        if (child > Nn) child = Nn;
        hs[m][kk] = g_h[(size_t)child * Hd + kw + kk];
    }
    __syncthreads();

    float acc[B];
#pragma unroll
    for (int m = 0; m < B; m++) acc[m] = 0.0f;
    const float* Wj = W + (size_t)j * Hd + kw;
#pragma unroll
    for (int t = 0; t < 8; t++) {
        int kk = t * 32 + lane;
        float w = Wj[kk];
#pragma unroll
        for (int m = 0; m < B; m++) acc[m] += w * hs[m][kk];
    }
#pragma unroll
    for (int m = 0; m < B; m++) {
        float v = acc[m];
#pragma unroll
        for (int off = 16; off; off >>= 1) v += __shfl_xor_sync(0xffffffffu, v, off);
        if (lane == 0) g_part[(size_t)(blockIdx.y * 32 + m) * G6 + j] = v;
    }
}

// ---------------------------------------------------------------------------
// Elementwise node update for a chunk [start, start+B)
// ---------------------------------------------------------------------------
__global__ void update_kernel(float* __restrict__ out, int start, int B, int has_part) {
    int idx = blockIdx.x * 256 + threadIdx.x;
    if (idx >= B * Hd) return;
    int m = idx >> 10, j = idx & (Hd - 1);
    int i = start + m;
    const float* gx = g_xg + (size_t)i * G6;
    float gi = gx[j], go = gx[Hd + j], gfl = gx[2 * Hd + j],
          gfr = gx[3 * Hd + j], gu = gx[4 * Hd + j], gr = gx[5 * Hd + j];
    if (has_part) {
#pragma unroll
        for (int kb = 0; kb < 8; kb++) {
            const float* p = g_part + (size_t)(kb * 32 + m) * G6;
            gi += p[j]; go += p[Hd + j]; gfl += p[2 * Hd + j];
            gfr += p[3 * Hd + j]; gu += p[4 * Hd + j]; gr += p[5 * Hd + j];
        }
    }
    int l = 2 * i + 1; if (l > Nn) l = Nn;
    int r = 2 * i + 2; if (r > Nn) r = Nn;
    float cl = g_c[(size_t)l * Hd + j];
    float cr = g_c[(size_t)r * Hd + j];
    float ig = sigmoidf_(gi), og = sigmoidf_(go);
    float fl = sigmoidf_(gfl), fr = sigmoidf_(gfr);
    float rr = sigmoidf_(gr);
    float u  = tanhf(gu);
    float c  = ig * u + fl * cl + fr * cr;
    float h  = og * tanhf(c);
    float px = g_px[(size_t)i * Hd + j];
    float hf = rr * h + (1.0f - rr) * px;
    g_c[(size_t)i * Hd + j] = c;
    g_h[(size_t)i * Hd + j] = hf;
    out[(size_t)i * Hd + j] = hf;
}

// ---------------------------------------------------------------------------
extern "C" void kernel_launch(void* const* d_in, const int* in_sizes, int n_in,
                              void* d_out, int out_size) {
    const float* features = (const float*)d_in[0];
    const float* w_x = (const float*)d_in[1];
    const float* b_x = (const float*)d_in[2];
    const float* w_l = (const float*)d_in[3];
    const float* b_l = (const float*)d_in[4];
    const float* w_r = (const float*)d_in[5];
    const float* b_r = (const float*)d_in[6];
    const float* w_p = (const float*)d_in[7];
    const float* b_p = (const float*)d_in[8];
    float* out = (float*)d_out;
    (void)in_sizes; (void)n_in; (void)out_size;

    init_kernel<<<24, 256>>>(b_x, b_l, b_r);

    // x projections: g_xg = feat @ w_x^T + (b_x + b_l + b_r) ; g_px = feat @ w_p^T + b_p
    sgemm_xproj<<<dim3(G6 / 128, Nn / 128), 256>>>(features, w_x, nullptr, 0);
    sgemm_xproj<<<dim3(Hd / 128, Nn / 128), 256>>>(features, w_p, b_p, 1);

    // Leaf level [1024, 2048): children are zero -> no recurrent GEMM
    update_kernel<<<(1024 * Hd) / 256, 256>>>(out, 1024, 1024, 0);

    // Mid levels: batched recurrent GEMM chunks
    for (int a = 512; a >= 64; a >>= 1) {
        chunk_gemm<<<dim3(G6 / 64, a / 64), 256>>>(w_l, w_r, a);
        update_kernel<<<(a * Hd) / 256, 256>>>(out, a, a, 0);
    }

    // Small levels: K-split GEMV + partial reduction in update
    chunk_small<32><<<dim3(G6 / 8, 8), 256>>>(w_l, w_r, 32);
    update_kernel<<<(32 * Hd) / 256, 256>>>(out, 32, 32, 1);
    chunk_small<16><<<dim3(G6 / 8, 8), 256>>>(w_l, w_r, 16);
    update_kernel<<<(16 * Hd) / 256, 256>>>(out, 16, 16, 1);
    chunk_small<8><<<dim3(G6 / 8, 8), 256>>>(w_l, w_r, 8);
    update_kernel<<<(8 * Hd) / 256, 256>>>(out, 8, 8, 1);
    chunk_small<4><<<dim3(G6 / 8, 8), 256>>>(w_l, w_r, 4);
    update_kernel<<<(4 * Hd) / 256, 256>>>(out, 4, 4, 1);
    chunk_small<2><<<dim3(G6 / 8, 8), 256>>>(w_l, w_r, 2);
    update_kernel<<<(2 * Hd) / 256, 256>>>(out, 2, 2, 1);
    chunk_small<1><<<dim3(G6 / 8, 8), 256>>>(w_l, w_r, 1);
    update_kernel<<<(1 * Hd) / 256, 256>>>(out, 1, 1, 1);
    chunk_small<1><<<dim3(G6 / 8, 8), 256>>>(w_l, w_r, 0);  // root node 0
    update_kernel<<<(1 * Hd) / 256, 256>>>(out, 0, 1, 1);
}

// round 3
// speedup vs baseline: 1.0023x; 1.0023x over previous
#include <cuda_runtime.h>
#include <math.h>

#define Nn 2048
#define FD 2048
#define Hd 1024
#define G6 6144

// Persistent scratch (static device globals — no allocation at launch time).
__device__ float g_xg[(size_t)Nn * G6];        // x_gates (+ all biases), later += h-contributions
__device__ float g_px[(size_t)Nn * Hd];        // px projection
__device__ float g_c [(size_t)(Nn + 1) * Hd];  // cell state, row Nn = zero sentinel
__device__ float g_h [(size_t)(Nn + 1) * Hd];  // hidden state, row Nn = zero sentinel
__device__ float g_bias6[G6];                  // b_ioffux + b_ioffuh_l + b_ioffuh_r
__device__ float g_part[8 * 32 * G6];          // k-split partials for small chunks

// ---------------------------------------------------------------------------
// packed f32x2 helpers (FFMA2: 2 fp32 MACs per instruction on sm_100+)
// ---------------------------------------------------------------------------
__device__ __forceinline__ void fma2(unsigned long long& c, unsigned long long a,
                                     unsigned long long b) {
    asm("fma.rn.f32x2 %0, %1, %2, %0;" : "+l"(c) : "l"(a), "l"(b));
}
__device__ __forceinline__ unsigned long long dup2(float x) {
    unsigned long long d;
    asm("mov.b64 %0, {%1, %1};" : "=l"(d) : "f"(x));
    return d;
}
__device__ __forceinline__ float lo2(unsigned long long v) {
    return __uint_as_float((unsigned int)v);
}
__device__ __forceinline__ float hi2(unsigned long long v) {
    return __uint_as_float((unsigned int)(v >> 32));
}

__device__ __forceinline__ float sigmoidf_(float x) { return 1.0f / (1.0f + expf(-x)); }

// ---------------------------------------------------------------------------
// init: combine biases, zero sentinel state rows
// ---------------------------------------------------------------------------
__global__ void init_kernel(const float* __restrict__ bx, const float* __restrict__ bl,
                            const float* __restrict__ br) {
    int j = blockIdx.x * 256 + threadIdx.x;
    if (j < G6) g_bias6[j] = bx[j] + bl[j] + br[j];
    if (j < Hd) {
        g_c[(size_t)Nn * Hd + j] = 0.0f;
        g_h[(size_t)Nn * Hd + j] = 0.0f;
    }
}

// ---------------------------------------------------------------------------
// Big NT SGEMM: C[M,Nc] = A[M,K] * W[Nc,K]^T + bias   (128x128x16 tile, FFMA2)
// target==0: C=g_xg, Nc=6144, bias=g_bias6 ; target==1: C=g_px, Nc=1024, bias=bias_ext
// ---------------------------------------------------------------------------
__global__ __launch_bounds__(256) void sgemm_xproj(const float* __restrict__ A,
                                                   const float* __restrict__ W,
                                                   const float* __restrict__ bias_ext,
                                                   int target) {
    __shared__ float As[16][128];
    __shared__ float Bs[16][128];
    const int tid = threadIdx.x;
    const int tx = tid & 15, ty = tid >> 4;
    const float* Ag = A + (size_t)blockIdx.y * 128 * FD;
    const float* Wg = W + (size_t)blockIdx.x * 128 * FD;

    unsigned long long acc[8][4];
#pragma unroll
    for (int i = 0; i < 8; i++)
#pragma unroll
        for (int j = 0; j < 4; j++) acc[i][j] = 0ull;

    for (int k0 = 0; k0 < FD; k0 += 16) {
        __syncthreads();
#pragma unroll
        for (int l = 0; l < 2; l++) {
            int idx = tid + l * 256;
            int row = idx >> 2;
            int c4  = (idx & 3) << 2;
            float4 av = *(const float4*)(Ag + (size_t)row * FD + k0 + c4);
            As[c4 + 0][row] = av.x; As[c4 + 1][row] = av.y;
            As[c4 + 2][row] = av.z; As[c4 + 3][row] = av.w;
            float4 bv = *(const float4*)(Wg + (size_t)row * FD + k0 + c4);
            Bs[c4 + 0][row] = bv.x; Bs[c4 + 1][row] = bv.y;
            Bs[c4 + 2][row] = bv.z; Bs[c4 + 3][row] = bv.w;
        }
        __syncthreads();
#pragma unroll
        for (int k = 0; k < 16; k++) {
            float a[8];
            *(float4*)(a)     = *(const float4*)&As[k][ty * 4];
            *(float4*)(a + 4) = *(const float4*)&As[k][64 + ty * 4];
            ulonglong2 u0 = *(const ulonglong2*)&Bs[k][tx * 4];
            ulonglong2 u1 = *(const ulonglong2*)&Bs[k][64 + tx * 4];
            unsigned long long b2[4] = {u0.x, u0.y, u1.x, u1.y};
#pragma unroll
            for (int i = 0; i < 8; i++) {
                unsigned long long ad = dup2(a[i]);
                fma2(acc[i][0], ad, b2[0]);
                fma2(acc[i][1], ad, b2[1]);
                fma2(acc[i][2], ad, b2[2]);
                fma2(acc[i][3], ad, b2[3]);
            }
        }
    }

    float* C = target ? g_px : g_xg;
    const int Nc = target ? Hd : G6;
    const float* bias = target ? bias_ext : g_bias6;
#pragma unroll
    for (int i = 0; i < 8; i++) {
        int rr = (i < 4) ? (ty * 4 + i) : (64 + ty * 4 + (i - 4));
        int grow = blockIdx.y * 128 + rr;
#pragma unroll
        for (int j2 = 0; j2 < 4; j2++) {
            int cc = (j2 < 2) ? (tx * 4 + j2 * 2) : (64 + tx * 4 + (j2 - 2) * 2);
            int gcol = blockIdx.x * 128 + cc;
            float2 v;
            v.x = lo2(acc[i][j2]) + bias[gcol];
            v.y = hi2(acc[i][j2]) + bias[gcol + 1];
            *(float2*)&C[(size_t)grow * Nc + gcol] = v;
        }
    }
}

// ---------------------------------------------------------------------------
// Recurrent chunk GEMM (B multiple of 64): g_xg[i,:] += h[l(i)] @ WL^T + h[r(i)] @ WR^T
// A rows gathered implicitly from g_h via child index. 64x64x16 tile, FFMA2.
// grid: (6144/64, B/64)
// ---------------------------------------------------------------------------
__global__ __launch_bounds__(256) void chunk_gemm(const float* __restrict__ WL,
                                                  const float* __restrict__ WR,
                                                  int start) {
    __shared__ float As[16][64];
    __shared__ float Bs[16][64];
    const int tid = threadIdx.x;
    const int tx = tid & 15, ty = tid >> 4;

    unsigned long long acc[4][2];
#pragma unroll
    for (int i = 0; i < 4; i++) { acc[i][0] = 0ull; acc[i][1] = 0ull; }

    for (int k0 = 0; k0 < 2 * Hd; k0 += 16) {
        const float* W = (k0 < Hd) ? WL : WR;
        const int kk = k0 & (Hd - 1);
        __syncthreads();
        {
            int row = tid >> 2;
            int c4  = (tid & 3) << 2;
            int i = start + blockIdx.y * 64 + row;
            int child = (k0 < Hd) ? (2 * i + 1) : (2 * i + 2);
            if (child > Nn) child = Nn;  // sentinel (zeros)
            float4 av = *(const float4*)(g_h + (size_t)child * Hd + kk + c4);
            As[c4 + 0][row] = av.x; As[c4 + 1][row] = av.y;
            As[c4 + 2][row] = av.z; As[c4 + 3][row] = av.w;
            float4 bv = *(const float4*)(W + (size_t)(blockIdx.x * 64 + row) * Hd + kk + c4);
            Bs[c4 + 0][row] = bv.x; Bs[c4 + 1][row] = bv.y;
            Bs[c4 + 2][row] = bv.z; Bs[c4 + 3][row] = bv.w;
        }
        __syncthreads();
#pragma unroll
        for (int k = 0; k < 16; k++) {
            float4 af = *(const float4*)&As[k][ty * 4];
            ulonglong2 u0 = *(const ulonglong2*)&Bs[k][tx * 4];
            float a[4] = {af.x, af.y, af.z, af.w};
#pragma unroll
            for (int i = 0; i < 4; i++) {
                unsigned long long ad = dup2(a[i]);
                fma2(acc[i][0], ad, u0.x);
                fma2(acc[i][1], ad, u0.y);
            }
        }
    }
#pragma unroll
    for (int i = 0; i < 4; i++) {
        int grow = start + blockIdx.y * 64 + ty * 4 + i;
        float* Cp = g_xg + (size_t)grow * G6 + blockIdx.x * 64 + tx * 4;
        Cp[0] += lo2(acc[i][0]);
        Cp[1] += hi2(acc[i][0]);
        Cp[2] += lo2(acc[i][1]);
        Cp[3] += hi2(acc[i][1]);
    }
}

// ---------------------------------------------------------------------------
// Small chunk (B <= 32): K-split GEMV. grid (6144/8, 8); each warp owns one gate
// output j, computes partials over a 256-wide K slice for all B nodes.
// h slabs staged in shared memory. Partials summed in update_kernel.
// ---------------------------------------------------------------------------
template <int B>
__global__ __launch_bounds__(256) void chunk_small(const float* __restrict__ WL,
                                                   const float* __restrict__ WR,
                                                   int start) {
    __shared__ float hs[B][256];
    const int warp = threadIdx.x >> 5, lane = threadIdx.x & 31;
    const int j  = blockIdx.x * 8 + warp;
    const int ks = blockIdx.y * 256;
    const float* W = (ks < Hd) ? WL : WR;
    const int kw = ks & (Hd - 1);

    for (int idx = threadIdx.x; idx < B * 256; idx += 256) {
        int m = idx >> 8, kk = idx & 255;
        int i = start + m;
        int child = (ks < Hd) ? (2 * i + 1) : (2 * i + 2);
        if (child > Nn) child = Nn;
        hs[m][kk] = g_h[(size_t)child * Hd + kw + kk];
    }
    __syncthreads();

    float acc[B];
#pragma unroll
    for (int m = 0; m < B; m++) acc[m] = 0.0f;
    const float* Wj = W + (size_t)j * Hd + kw;
#pragma unroll
    for (int t = 0; t < 8; t++) {
        int kk = t * 32 + lane;
        float w = Wj[kk];
#pragma unroll
        for (int m = 0; m < B; m++) acc[m] += w * hs[m][kk];
    }
#pragma unroll
    for (int m = 0; m < B; m++) {
        float v = acc[m];
#pragma unroll
        for (int off = 16; off; off >>= 1) v += __shfl_xor_sync(0xffffffffu, v, off);
        if (lane == 0) g_part[(size_t)(blockIdx.y * 32 + m) * G6 + j] = v;
    }
}

// ---------------------------------------------------------------------------
// Elementwise node update for a chunk [start, start+B)
// ---------------------------------------------------------------------------
__global__ void update_kernel(float* __restrict__ out, int start, int B, int has_part) {
    int idx = blockIdx.x * 256 + threadIdx.x;
    if (idx >= B * Hd) return;
    int m = idx >> 10, j = idx & (Hd - 1);
    int i = start + m;
    const float* gx = g_xg + (size_t)i * G6;
    float gi = gx[j], go = gx[Hd + j], gfl = gx[2 * Hd + j],
          gfr = gx[3 * Hd + j], gu = gx[4 * Hd + j], gr = gx[5 * Hd + j];
    if (has_part) {
#pragma unroll
        for (int kb = 0; kb < 8; kb++) {
            const float* p = g_part + (size_t)(kb * 32 + m) * G6;
            gi += p[j]; go += p[Hd + j]; gfl += p[2 * Hd + j];
            gfr += p[3 * Hd + j]; gu += p[4 * Hd + j]; gr += p[5 * Hd + j];
        }
    }
    int l = 2 * i + 1; if (l > Nn) l = Nn;
    int r = 2 * i + 2; if (r > Nn) r = Nn;
    float cl = g_c[(size_t)l * Hd + j];
    float cr = g_c[(size_t)r * Hd + j];
    float ig = sigmoidf_(gi), og = sigmoidf_(go);
    float fl = sigmoidf_(gfl), fr = sigmoidf_(gfr);
    float rr = sigmoidf_(gr);
    float u  = tanhf(gu);
    float c  = ig * u + fl * cl + fr * cr;
    float h  = og * tanhf(c);
    float px = g_px[(size_t)i * Hd + j];
    float hf = rr * h + (1.0f - rr) * px;
    g_c[(size_t)i * Hd + j] = c;
    g_h[(size_t)i * Hd + j] = hf;
    out[(size_t)i * Hd + j] = hf;
}

// ---------------------------------------------------------------------------
extern "C" void kernel_launch(void* const* d_in, const int* in_sizes, int n_in,
                              void* d_out, int out_size) {
    const float* features = (const float*)d_in[0];
    const float* w_x = (const float*)d_in[1];
    const float* b_x = (const float*)d_in[2];
    const float* w_l = (const float*)d_in[3];
    const float* b_l = (const float*)d_in[4];
    const float* w_r = (const float*)d_in[5];
    const float* b_r = (const float*)d_in[6];
    const float* w_p = (const float*)d_in[7];
    const float* b_p = (const float*)d_in[8];
    float* out = (float*)d_out;
    (void)in_sizes; (void)n_in; (void)out_size;

    init_kernel<<<24, 256>>>(b_x, b_l, b_r);

    // x projections: g_xg = feat @ w_x^T + (b_x + b_l + b_r) ; g_px = feat @ w_p^T + b_p
    sgemm_xproj<<<dim3(G6 / 128, Nn / 128), 256>>>(features, w_x, nullptr, 0);
    sgemm_xproj<<<dim3(Hd / 128, Nn / 128), 256>>>(features, w_p, b_p, 1);

    // Leaf level [1024, 2048): children are zero -> no recurrent GEMM
    update_kernel<<<(1024 * Hd) / 256, 256>>>(out, 1024, 1024, 0);

    // Mid levels: batched recurrent GEMM chunks
    for (int a = 512; a >= 64; a >>= 1) {
        chunk_gemm<<<dim3(G6 / 64, a / 64), 256>>>(w_l, w_r, a);
        update_kernel<<<(a * Hd) / 256, 256>>>(out, a, a, 0);
    }

    // Small levels: K-split GEMV + partial reduction in update
    chunk_small<32><<<dim3(G6 / 8, 8), 256>>>(w_l, w_r, 32);
    update_kernel<<<(32 * Hd) / 256, 256>>>(out, 32, 32, 1);
    chunk_small<16><<<dim3(G6 / 8, 8), 256>>>(w_l, w_r, 16);
    update_kernel<<<(16 * Hd) / 256, 256>>>(out, 16, 16, 1);
    chunk_small<8><<<dim3(G6 / 8, 8), 256>>>(w_l, w_r, 8);
    update_kernel<<<(8 * Hd) / 256, 256>>>(out, 8, 8, 1);
    chunk_small<4><<<dim3(G6 / 8, 8), 256>>>(w_l, w_r, 4);
    update_kernel<<<(4 * Hd) / 256, 256>>>(out, 4, 4, 1);
    chunk_small<2><<<dim3(G6 / 8, 8), 256>>>(w_l, w_r, 2);
    update_kernel<<<(2 * Hd) / 256, 256>>>(out, 2, 2, 1);
    chunk_small<1><<<dim3(G6 / 8, 8), 256>>>(w_l, w_r, 1);
    update_kernel<<<(1 * Hd) / 256, 256>>>(out, 1, 1, 1);
    chunk_small<1><<<dim3(G6 / 8, 8), 256>>>(w_l, w_r, 0);  // root node 0
    update_kernel<<<(1 * Hd) / 256, 256>>>(out, 0, 1, 1);
}